// round 11
// baseline (speedup 1.0000x reference)
#include <cuda_runtime.h>
#include <cuda_fp16.h>
#include <cstdint>
#include <math.h>

#define HIDDEN 2048
#define NHEADS 16
#define HD 128
#define RD 64
#define DQK 192
#define KVC 512
#define QC 1536
#define BATCH 2
#define SEQ 2048
#define ROWS (BATCH*SEQ)   // 4096

// ---------------- scratch (static device memory; no allocation allowed) -----
// attention operands [B,H,S,*], fp16
__device__ __half g_Qh[(size_t)BATCH*NHEADS*SEQ*DQK];
__device__ __half g_Kh[(size_t)BATCH*NHEADS*SEQ*DQK];
__device__ __half g_Vh[(size_t)BATCH*NHEADS*SEQ*HD];

// fp16 activations
__device__ __half g_xh [ROWS*HIDDEN];
__device__ __half g_kvch[ROWS*KVC];
__device__ __half g_qlh [ROWS*QC];
__device__ __half g_cxh [ROWS*NHEADS*HD];

// weights transposed to [N][K], fp16.  kv-up fused: [kuw | vuw | krw] rows.
__device__ __half g_kvdwh[KVC*HIDDEN];
__device__ __half g_kvwf [(2048 + 2048 + 1024) * KVC];   // N=5120, K=512
__device__ __half g_qdwh [QC*HIDDEN];
__device__ __half g_qwf  [(2048 + 1024) * QC];           // N=3072, K=1536
__device__ __half g_owh  [HIDDEN*NHEADS*HD];

// ======================= mma / ldmatrix helpers =============================
__device__ __forceinline__ uint32_t s2u(const void* p) {
    return (uint32_t)__cvta_generic_to_shared(p);
}
__device__ __forceinline__ void ldsm4(uint32_t* r, uint32_t addr) {
    asm volatile("ldmatrix.sync.aligned.m8n8.x4.shared.b16 {%0,%1,%2,%3}, [%4];"
                 : "=r"(r[0]), "=r"(r[1]), "=r"(r[2]), "=r"(r[3]) : "r"(addr));
}
__device__ __forceinline__ void ldsm4t(uint32_t* r, uint32_t addr) {
    asm volatile("ldmatrix.sync.aligned.m8n8.x4.trans.shared.b16 {%0,%1,%2,%3}, [%4];"
                 : "=r"(r[0]), "=r"(r[1]), "=r"(r[2]), "=r"(r[3]) : "r"(addr));
}
__device__ __forceinline__ void mmah(float* c, const uint32_t* a, const uint32_t* b) {
    asm volatile(
        "mma.sync.aligned.m16n8k16.row.col.f32.f16.f16.f32 "
        "{%0,%1,%2,%3}, {%4,%5,%6,%7}, {%8,%9}, {%0,%1,%2,%3};"
        : "+f"(c[0]), "+f"(c[1]), "+f"(c[2]), "+f"(c[3])
        : "r"(a[0]), "r"(a[1]), "r"(a[2]), "r"(a[3]), "r"(b[0]), "r"(b[1]));
}
__device__ __forceinline__ void mmahs(float* c, const uint32_t* a, uint32_t b0, uint32_t b1) {
    asm volatile(
        "mma.sync.aligned.m16n8k16.row.col.f32.f16.f16.f32 "
        "{%0,%1,%2,%3}, {%4,%5,%6,%7}, {%8,%9}, {%0,%1,%2,%3};"
        : "+f"(c[0]), "+f"(c[1]), "+f"(c[2]), "+f"(c[3])
        : "r"(a[0]), "r"(a[1]), "r"(a[2]), "r"(a[3]), "r"(b0), "r"(b1));
}
__device__ __forceinline__ void cpasync16(uint32_t dst, const void* src) {
    asm volatile("cp.async.cg.shared.global [%0], [%1], 16;"
                 :: "r"(dst), "l"(src) : "memory");
}
__device__ __forceinline__ uint32_t pack2h(float x, float y) {
    __half2 t = __floats2half2_rn(x, y);
    return *(uint32_t*)&t;
}
__device__ __forceinline__ void whi2(__half* __restrict__ H, size_t o, float a, float b) {
    *(__half2*)&H[o] = __floats2half2_rn(a, b);
}

// ======================= fp32 -> fp16 convert ===============================
__global__ void conv_half(const float* __restrict__ s, __half* __restrict__ h, int n)
{
    int i = (blockIdx.x * blockDim.x + threadIdx.x) * 4;
    if (i >= n) return;
    float4 v = *(const float4*)(s + i);
    *(__half2*)(h + i)     = __floats2half2_rn(v.x, v.y);
    *(__half2*)(h + i + 2) = __floats2half2_rn(v.z, v.w);
}

// ======= fused transpose: 8 matrices, src[K][N] fp32 -> dst [N][K] fp16 =====
struct TSpec { const float* src; __half* dst; int K; int N; int blk0; };
struct TTab  { TSpec e[8]; };

__global__ void transpose_all(TTab tab)
{
    __shared__ float t[32][33];
    int b = blockIdx.x;
    int ei = 0;
#pragma unroll
    for (int i = 1; i < 8; i++)
        if (b >= tab.e[i].blk0) ei = i;
    const TSpec sp = tab.e[ei];
    int lb = b - sp.blk0;
    int nbx = sp.N >> 5;
    int nb = (lb % nbx) * 32;
    int kb = (lb / nbx) * 32;

    int tx = threadIdx.x, ty = threadIdx.y;    // 32 x 8
#pragma unroll
    for (int i = 0; i < 32; i += 8)
        t[ty + i][tx] = sp.src[(size_t)(kb + ty + i) * sp.N + nb + tx];
    __syncthreads();
#pragma unroll
    for (int i = 0; i < 32; i += 8)
        sp.dst[(size_t)(nb + ty + i) * sp.K + kb + tx] = __float2half_rn(t[tx][ty + i]);
}

// ======================= HMMA fp16 GEMM =====================================
// C[M,N] = Ah[M,K] @ Bh[N,K]^T + bias.  CTA 128x128, 4 warps (warp tile 64x64),
// BK=32, 3-stage cp.async, 2 CTAs/SM.  Epilogue modes:
//   0 = fp32 C [M,N]
//   1 = fp16 Ch [M,N]
//   5 = fused kv:  col<2048 -> Kh[B,H,S,192] (bias biasA)
//                  col<4096 -> Vh=Ch2 [B,H,S,128] (biasB)
//                  else     -> RoPE -> Kh[...,128+d] (biasR)
//   6 = fused q:   col<2048 -> Qh[B,H,S,192] (biasA)
//                  else     -> RoPE -> Qh[...,128+d] (biasR)
#define BKP 40
#define MAT_SMEM (128*BKP*2)      // 10240
#define STG_SMEM (2*MAT_SMEM)     // 20480
#define GEMM_SMEM (3*STG_SMEM)    // 61440

__global__ void __launch_bounds__(128, 2) gemm_hmma1(
    const __half* __restrict__ Ah, const __half* __restrict__ Bh,
    const float* __restrict__ biasA, const float* __restrict__ biasB,
    const float* __restrict__ biasR,
    float* __restrict__ C,
    __half* __restrict__ Ch, __half* __restrict__ Ch2,
    int M, int N, int K, int mode)
{
    extern __shared__ char dsm[];
    const uint32_t sbase = s2u(dsm);

    const int tid  = threadIdx.x;
    const int warp = tid >> 5, lane = tid & 31;
    const int wm = (warp & 1) * 64;
    const int wn = (warp >> 1) * 64;
    const int m0 = blockIdx.y * 128, n0 = blockIdx.x * 128;

    const __half* gM[2] = { Ah + (size_t)m0 * K, Bh + (size_t)n0 * K };

    const int nK = K >> 5;

    const int a_r  = lane & 15;
    const int a_c8 = (lane >> 4) << 3;
    const int b_r  = (lane & 7) + ((lane >> 4) << 3);
    const int b_c8 = (lane & 8) ? 8 : 0;

    float acc[4][8][4];
#pragma unroll
    for (int mt = 0; mt < 4; mt++)
#pragma unroll
        for (int nt = 0; nt < 8; nt++)
#pragma unroll
            for (int q = 0; q < 4; q++) acc[mt][nt][q] = 0.f;

    auto load_stage = [&](int stg, int kb) {
        uint32_t sb = sbase + stg * STG_SMEM;
#pragma unroll
        for (int mat = 0; mat < 2; mat++) {
            const __half* g = gM[mat];
#pragma unroll
            for (int j = 0; j < 4; j++) {
                int c = tid + j * 128;
                int row = c >> 2, c16 = c & 3;
                cpasync16(sb + mat * MAT_SMEM + (row * BKP + c16 * 8) * 2,
                          g + (size_t)row * K + kb + c16 * 8);
            }
        }
        asm volatile("cp.async.commit_group;" ::: "memory");
    };

    load_stage(0, 0);
    load_stage(1, 32);

    int cur = 0, nxt = 2;
    for (int i = 0; i < nK; i++) {
        if (i + 1 < nK) asm volatile("cp.async.wait_group 1;" ::: "memory");
        else            asm volatile("cp.async.wait_group 0;" ::: "memory");
        __syncthreads();
        if (i + 2 < nK) load_stage(nxt, (i + 2) * 32);

        const uint32_t sAh = sbase + cur * STG_SMEM;
        const uint32_t sBh = sAh + MAT_SMEM;

#pragma unroll
        for (int kk = 0; kk < 32; kk += 16) {
            uint32_t ah[4][4], bh[4][4];
#pragma unroll
            for (int mt = 0; mt < 4; mt++) {
                uint32_t off = ((wm + mt * 16 + a_r) * BKP + kk + a_c8) * 2;
                ldsm4(ah[mt], sAh + off);
            }
#pragma unroll
            for (int p = 0; p < 4; p++) {
                uint32_t off = ((wn + p * 16 + b_r) * BKP + kk + b_c8) * 2;
                ldsm4(bh[p], sBh + off);
            }
#pragma unroll
            for (int mt = 0; mt < 4; mt++)
#pragma unroll
                for (int nt = 0; nt < 8; nt++)
                    mmah(acc[mt][nt], ah[mt], &bh[nt >> 1][(nt & 1) * 2]);
        }
        cur = (cur == 2) ? 0 : cur + 1;
        nxt = (nxt == 2) ? 0 : nxt + 1;
    }

    // ---- epilogue ----
    const int er = lane >> 2, ec = (lane & 3) * 2;
#pragma unroll
    for (int mt = 0; mt < 4; mt++) {
#pragma unroll
        for (int nt = 0; nt < 8; nt++) {
            int col = n0 + wn + nt * 8 + ec;
            int r0 = m0 + wm + mt * 16 + er;
            int r1 = r0 + 8;
            float p0 = acc[mt][nt][0], p1 = acc[mt][nt][1];
            float p2 = acc[mt][nt][2], p3 = acc[mt][nt][3];
            if (mode == 0) {
                float b0 = biasA[col], b1 = biasA[col + 1];
                *(float2*)&C[(size_t)r0 * N + col] = make_float2(p0 + b0, p1 + b1);
                *(float2*)&C[(size_t)r1 * N + col] = make_float2(p2 + b0, p3 + b1);
            } else if (mode == 1) {
                float b0 = biasA[col], b1 = biasA[col + 1];
                whi2(Ch, (size_t)r0 * N + col, p0 + b0, p1 + b1);
                whi2(Ch, (size_t)r1 * N + col, p2 + b0, p3 + b1);
            } else {
                const int rb = (mode == 5) ? 4096 : 2048;
                if (col < 2048) {
                    // K or Q core part -> [B,H,S,192]
                    float b0 = biasA[col], b1 = biasA[col + 1];
                    int hh = col >> 7, d = col & 127;
                    size_t o0 = (((size_t)(r0 >> 11) * NHEADS + hh) * SEQ + (r0 & 2047)) * DQK + d;
                    size_t o1 = (((size_t)(r1 >> 11) * NHEADS + hh) * SEQ + (r1 & 2047)) * DQK + d;
                    whi2(Ch, o0, p0 + b0, p1 + b1);
                    whi2(Ch, o1, p2 + b0, p3 + b1);
                } else if (mode == 5 && col < 4096) {
                    // V -> [B,H,S,128]
                    int c2 = col - 2048;
                    float b0 = biasB[c2], b1 = biasB[c2 + 1];
                    int hh = c2 >> 7, d = c2 & 127;
                    size_t o0 = (((size_t)(r0 >> 11) * NHEADS + hh) * SEQ + (r0 & 2047)) * HD + d;
                    size_t o1 = (((size_t)(r1 >> 11) * NHEADS + hh) * SEQ + (r1 & 2047)) * HD + d;
                    whi2(Ch2, o0, p0 + b0, p1 + b1);
                    whi2(Ch2, o1, p2 + b0, p3 + b1);
                } else {
                    // rope part: rotate pair and store at DQK offset 128+d2
                    int c2 = col - rb;
                    float b0 = biasR[c2], b1 = biasR[c2 + 1];
                    int hh = c2 >> 6, d2 = c2 & 63;
                    float x0 = p0 + b0, x1 = p1 + b1;   // row r0: (2i, 2i+1)
                    float y0 = p2 + b0, y1 = p3 + b1;   // row r1
                    int s0 = r0 & 2047, s1 = r1 & 2047;
                    float inv_freq = powf(10000.f, -(float)d2 / 64.f);
                    float sn0, cs0, sn1, cs1;
                    sincosf((float)s0 * inv_freq, &sn0, &cs0);
                    sincosf((float)s1 * inv_freq, &sn1, &cs1);
                    size_t o0 = (((size_t)(r0 >> 11) * NHEADS + hh) * SEQ + s0) * DQK + HD + d2;
                    size_t o1 = (((size_t)(r1 >> 11) * NHEADS + hh) * SEQ + s1) * DQK + HD + d2;
                    whi2(Ch, o0, x0*cs0 - x1*sn0, x0*sn0 + x1*cs0);
                    whi2(Ch, o1, y0*cs1 - y1*sn1, y0*sn1 + y1*cs1);
                }
            }
        }
    }
}

// ============== HMMA fp16 causal flash attention ============================
// CTA: 128 queries x full head. 8 warps, warp = 16 query rows.
// LPT: blockIdx.x reversed so heavy (high-q0) CTAs schedule first.
#define AQH 0
#define AKB(buf) (49152 + (buf)*24576)
#define AVB 98304
#define ATTN_SMEM 114688

__global__ void __launch_bounds__(256, 1) attn_hmma(
    const __half* __restrict__ Qhg,
    const __half* __restrict__ Khg, const __half* __restrict__ Vhg,
    __half* __restrict__ cxh)
{
    extern __shared__ char smc[];
    const uint32_t sb = s2u(smc);
    const int b = blockIdx.z, h = blockIdx.y;
    const int q0 = (gridDim.x - 1 - blockIdx.x) * 128;   // LPT: heavy first
    const int tid = threadIdx.x, w = tid >> 5, lane = tid & 31;
    const int ntiles = (q0 >> 6) + 2;

    const size_t hb = (size_t)(b*NHEADS + h) * SEQ;
    const __half* gQh = Qhg + (hb + q0) * DQK;
    const __half* gKh = Khg + hb * DQK;
    const __half* gVh = Vhg + hb * HD;

    auto ldQ = [&](uint32_t dst, const __half* g) {
        for (int i = tid; i < 128*24; i += 256) {
            int r = i / 24, c = i % 24;
            int cs = (c & ~7) | ((c ^ r) & 7);
            cpasync16(dst + (r*24 + cs)*16, g + r*192 + c*8);
        }
    };
    auto ldK = [&](uint32_t dst, const __half* g) {
        for (int i = tid; i < 64*24; i += 256) {
            int r = i / 24, c = i % 24;
            int cs = (c & ~7) | ((c ^ r) & 7);
            cpasync16(dst + (r*24 + cs)*16, g + r*192 + c*8);
        }
    };
    auto ldV = [&](uint32_t dst, const __half* g) {
        for (int i = tid; i < 64*16; i += 256) {
            int r = i / 16, c = i % 16;
            int cs = (c & ~7) | ((c ^ r) & 7);
            cpasync16(dst + (r*16 + cs)*16, g + r*128 + c*8);
        }
    };

    // prologue: group0 = {Q, K0, V0}, group1 = {K1}
    ldQ(sb + AQH, gQh);
    ldK(sb + AKB(0), gKh);
    ldV(sb + AVB,    gVh);
    asm volatile("cp.async.commit_group;" ::: "memory");
    ldK(sb + AKB(1), gKh + 64*192);
    asm volatile("cp.async.commit_group;" ::: "memory");

    float O[16][4];
#pragma unroll
    for (int t = 0; t < 16; t++)
#pragma unroll
        for (int j = 0; j < 4; j++) O[t][j] = 0.f;
    float m0r = -1e30f, m1r = -1e30f, l0 = 0.f, l1 = 0.f;

    const float scale = 0.07216878364870323f;  // 1/sqrt(192)
    const int lrow = lane & 15, lhi = lane >> 4;
    const int qr0 = q0 + w*16 + (lane >> 2);

    for (int i = 0; i < ntiles; i++) {
        const int k0 = i * 64;
        asm volatile("cp.async.wait_group 1;" ::: "memory");
        __syncthreads();

        const uint32_t kbh = sb + AKB(i & 1);

        float s[8][4];
#pragma unroll
        for (int t = 0; t < 8; t++)
#pragma unroll
            for (int j = 0; j < 4; j++) s[t][j] = 0.f;

        // ---- S = Q K^T ----
#pragma unroll
        for (int kc = 0; kc < 12; kc++) {
            uint32_t ah[4];
            {
                int r = w*16 + lrow;
                int c = kc*2 + lhi;
                int cs = (c & ~7) | ((c ^ r) & 7);
                ldsm4(ah, sb + AQH + (r*24 + cs)*16);
            }
#pragma unroll
            for (int kg = 0; kg < 4; kg++) {
                uint32_t bh[4];
                int r = kg*16 + lrow;
                int c = kc*2 + lhi;
                int cs = (c & ~7) | ((c ^ r) & 7);
                ldsm4(bh, kbh + (r*24 + cs)*16);
                mmahs(s[kg*2],   ah, bh[0], bh[2]);
                mmahs(s[kg*2+1], ah, bh[1], bh[3]);
            }
        }

        // ---- online softmax ----
        if (k0 + 63 > q0 + w*16) {
#pragma unroll
            for (int t = 0; t < 8; t++) {
                int kb = k0 + t*8 + ((lane & 3) << 1);
                s[t][0] = (kb     <= qr0    ) ? s[t][0]*scale : -1e30f;
                s[t][1] = (kb + 1 <= qr0    ) ? s[t][1]*scale : -1e30f;
                s[t][2] = (kb     <= qr0 + 8) ? s[t][2]*scale : -1e30f;
                s[t][3] = (kb + 1 <= qr0 + 8) ? s[t][3]*scale : -1e30f;
            }
        } else {
#pragma unroll
            for (int t = 0; t < 8; t++)
#pragma unroll
                for (int j = 0; j < 4; j++) s[t][j] *= scale;
        }

        float mx0 = -1e30f, mx1 = -1e30f;
#pragma unroll
        for (int t = 0; t < 8; t++) {
            mx0 = fmaxf(mx0, fmaxf(s[t][0], s[t][1]));
            mx1 = fmaxf(mx1, fmaxf(s[t][2], s[t][3]));
        }
        mx0 = fmaxf(mx0, __shfl_xor_sync(0xffffffffu, mx0, 1));
        mx0 = fmaxf(mx0, __shfl_xor_sync(0xffffffffu, mx0, 2));
        mx1 = fmaxf(mx1, __shfl_xor_sync(0xffffffffu, mx1, 1));
        mx1 = fmaxf(mx1, __shfl_xor_sync(0xffffffffu, mx1, 2));

        float mn0 = fmaxf(m0r, mx0), mn1 = fmaxf(m1r, mx1);
        float al0 = __expf(m0r - mn0), al1 = __expf(m1r - mn1);
        m0r = mn0; m1r = mn1;

        float sum0 = 0.f, sum1 = 0.f;
#pragma unroll
        for (int t = 0; t < 8; t++) {
            s[t][0] = __expf(s[t][0] - mn0); sum0 += s[t][0];
            s[t][1] = __expf(s[t][1] - mn0); sum0 += s[t][1];
            s[t][2] = __expf(s[t][2] - mn1); sum1 += s[t][2];
            s[t][3] = __expf(s[t][3] - mn1); sum1 += s[t][3];
        }
        l0 = l0*al0 + sum0;
        l1 = l1*al1 + sum1;
#pragma unroll
        for (int t = 0; t < 16; t++) {
            O[t][0] *= al0; O[t][1] *= al0;
            O[t][2] *= al1; O[t][3] *= al1;
        }

        // ---- O += P V ----
#pragma unroll
        for (int kc2 = 0; kc2 < 4; kc2++) {
            uint32_t pha[4];
            pha[0] = pack2h(s[kc2*2][0],   s[kc2*2][1]);
            pha[1] = pack2h(s[kc2*2][2],   s[kc2*2][3]);
            pha[2] = pack2h(s[kc2*2+1][0], s[kc2*2+1][1]);
            pha[3] = pack2h(s[kc2*2+1][2], s[kc2*2+1][3]);
#pragma unroll
            for (int dg = 0; dg < 8; dg++) {
                uint32_t vh[4];
                int r = kc2*16 + lrow;
                int c = dg*2 + lhi;
                int cs = (c & ~7) | ((c ^ r) & 7);
                ldsm4t(vh, sb + AVB + (r*16 + cs)*16);
                mmahs(O[dg*2],   pha, vh[0], vh[1]);
                mmahs(O[dg*2+1], pha, vh[2], vh[3]);
            }
        }
        __syncthreads();

        if (i + 1 < ntiles)
            ldV(sb + AVB, gVh + (size_t)(k0 + 64)*HD);
        asm volatile("cp.async.commit_group;" ::: "memory");
        if (i + 2 < ntiles)
            ldK(sb + AKB(i & 1), gKh + (size_t)(k0 + 128)*DQK);
        asm volatile("cp.async.commit_group;" ::: "memory");
    }

    l0 += __shfl_xor_sync(0xffffffffu, l0, 1);
    l0 += __shfl_xor_sync(0xffffffffu, l0, 2);
    l1 += __shfl_xor_sync(0xffffffffu, l1, 1);
    l1 += __shfl_xor_sync(0xffffffffu, l1, 2);
    float inv0 = 1.f / l0, inv1 = 1.f / l1;

#pragma unroll
    for (int t = 0; t < 16; t++) {
        int d = h*HD + t*8 + ((lane & 3) << 1);
        size_t ro0 = (size_t)(b*SEQ + qr0    ) * (NHEADS*HD) + d;
        size_t ro1 = (size_t)(b*SEQ + qr0 + 8) * (NHEADS*HD) + d;
        whi2(cxh, ro0, O[t][0]*inv0, O[t][1]*inv0);
        whi2(cxh, ro1, O[t][2]*inv1, O[t][3]*inv1);
    }
}

// ---------------- launch -----------------------------------------------------
static inline void gemm_m(const __half* Ah, const __half* Bh,
                          const float* bA, const float* bB, const float* bR,
                          float* C, __half* Ch, __half* Ch2,
                          int M, int N, int K, int mode)
{
    gemm_hmma1<<<dim3(N/128, M/128), 128, GEMM_SMEM>>>(
        Ah, Bh, bA, bB, bR, C, Ch, Ch2, M, N, K, mode);
}

extern "C" void kernel_launch(void* const* d_in, const int* in_sizes, int n_in,
                              void* d_out, int out_size)
{
    const float* x    = (const float*)d_in[0];
    const float* kvdw = (const float*)d_in[2];
    const float* kvdb = (const float*)d_in[3];
    const float* kuw  = (const float*)d_in[4];
    const float* kub  = (const float*)d_in[5];
    const float* vuw  = (const float*)d_in[6];
    const float* vub  = (const float*)d_in[7];
    const float* krw  = (const float*)d_in[8];
    const float* krb  = (const float*)d_in[9];
    const float* qdw  = (const float*)d_in[10];
    const float* qdb  = (const float*)d_in[11];
    const float* quw  = (const float*)d_in[12];
    const float* qub  = (const float*)d_in[13];
    const float* qrw  = (const float*)d_in[14];
    const float* qrb  = (const float*)d_in[15];
    const float* ow   = (const float*)d_in[16];
    const float* obv  = (const float*)d_in[17];
    float* out = (float*)d_out;

    __half *Qh,*Kh,*Vh;
    cudaGetSymbolAddress((void**)&Qh, g_Qh);
    cudaGetSymbolAddress((void**)&Kh, g_Kh);
    cudaGetSymbolAddress((void**)&Vh, g_Vh);

    __half *xh,*kvch,*qlh,*cxh;
    __half *kvdwh,*kvwf,*qdwh,*qwf,*owh;
    cudaGetSymbolAddress((void**)&xh, g_xh);
    cudaGetSymbolAddress((void**)&kvch, g_kvch);
    cudaGetSymbolAddress((void**)&qlh, g_qlh);
    cudaGetSymbolAddress((void**)&cxh, g_cxh);
    cudaGetSymbolAddress((void**)&kvdwh, g_kvdwh);
    cudaGetSymbolAddress((void**)&kvwf, g_kvwf);
    cudaGetSymbolAddress((void**)&qdwh, g_qdwh);
    cudaGetSymbolAddress((void**)&qwf, g_qwf);
    cudaGetSymbolAddress((void**)&owh, g_owh);

    cudaFuncSetAttribute(gemm_hmma1, cudaFuncAttributeMaxDynamicSharedMemorySize, GEMM_SMEM);
    cudaFuncSetAttribute(attn_hmma, cudaFuncAttributeMaxDynamicSharedMemorySize, ATTN_SMEM);

    // fused weight transpose (8 matrices in one launch; up-proj weights land
    // in the concatenated [N][K] buffers)
    {
        TTab tab;
        auto set = [&](int i, const float* s, __half* d, int K, int N, int blk0) {
            tab.e[i].src = s; tab.e[i].dst = d;
            tab.e[i].K = K; tab.e[i].N = N; tab.e[i].blk0 = blk0;
        };
        int b = 0;
        set(0, kvdw, kvdwh,                HIDDEN, KVC, b);        b += (KVC/32)*(HIDDEN/32);
        set(1, kuw,  kvwf,                 KVC, NHEADS*HD, b);     b += (NHEADS*HD/32)*(KVC/32);
        set(2, vuw,  kvwf + 2048*KVC,      KVC, NHEADS*HD, b);     b += (NHEADS*HD/32)*(KVC/32);
        set(3, krw,  kvwf + 4096*KVC,      KVC, NHEADS*RD, b);     b += (NHEADS*RD/32)*(KVC/32);
        set(4, qdw,  qdwh,                 HIDDEN, QC, b);         b += (QC/32)*(HIDDEN/32);
        set(5, quw,  qwf,                  QC, NHEADS*HD, b);      b += (NHEADS*HD/32)*(QC/32);
        set(6, qrw,  qwf + 2048*QC,        QC, NHEADS*RD, b);      b += (NHEADS*RD/32)*(QC/32);
        set(7, ow,   owh,                  NHEADS*HD, HIDDEN, b);  b += (HIDDEN/32)*(NHEADS*HD/32);
        transpose_all<<<b, dim3(32, 8)>>>(tab);
    }

    // x convert
    conv_half<<<ROWS*HIDDEN/4/256, 256>>>(x, xh, ROWS*HIDDEN);

    // kv path: down-proj, then fused up-projections (K | V | K-rope w/ RoPE)
    gemm_m(xh,   kvdwh, kvdb, nullptr, nullptr, nullptr, kvch, nullptr,
           ROWS, KVC, HIDDEN, 1);
    gemm_m(kvch, kvwf,  kub,  vub,     krb,     nullptr, Kh,   Vh,
           ROWS, 5120, KVC, 5);

    // q path: down-proj, then fused up-projections (Q | Q-rope w/ RoPE)
    gemm_m(xh,  qdwh, qdb, nullptr, nullptr, nullptr, qlh, nullptr,
           ROWS, QC, HIDDEN, 1);
    gemm_m(qlh, qwf,  qub, nullptr, qrb,     nullptr, Qh,  nullptr,
           ROWS, 3072, QC, 6);

    // attention (fp16 HMMA)
    attn_hmma<<<dim3(SEQ/128, NHEADS, BATCH), 256, ATTN_SMEM>>>(Qh, Kh, Vh, cxh);

    // output projection
    gemm_m(cxh, owh, obv, nullptr, nullptr, out, nullptr, nullptr,
           ROWS, HIDDEN, NHEADS*HD, 0);
}

// round 13
// speedup vs baseline: 1.1210x; 1.1210x over previous
#include <cuda_runtime.h>
#include <cuda_fp16.h>
#include <cstdint>
#include <math.h>

#define HIDDEN 2048
#define NHEADS 16
#define HD 128
#define RD 64
#define DQK 192
#define KVC 512
#define QC 1536
#define BATCH 2
#define SEQ 2048
#define ROWS (BATCH*SEQ)   // 4096

// ---------------- scratch (static device memory; no allocation allowed) -----
__device__ float g_kr [ROWS*NHEADS*RD];
__device__ float g_qru[ROWS*NHEADS*RD];

// attention operands [B,H,S,*], fp16
__device__ __half g_Qh[(size_t)BATCH*NHEADS*SEQ*DQK];
__device__ __half g_Kh[(size_t)BATCH*NHEADS*SEQ*DQK];
__device__ __half g_Vh[(size_t)BATCH*NHEADS*SEQ*HD];

// fp16 activations
__device__ __half g_xh [ROWS*HIDDEN];
__device__ __half g_kvch[ROWS*KVC];
__device__ __half g_qlh [ROWS*QC];
__device__ __half g_cxh [ROWS*NHEADS*HD];

// weights transposed to [N][K], fp16
__device__ __half g_kvdwh[KVC*HIDDEN];
__device__ __half g_kuwh [NHEADS*HD*KVC];
__device__ __half g_vuwh [NHEADS*HD*KVC];
__device__ __half g_krwh [NHEADS*RD*KVC];
__device__ __half g_qdwh [QC*HIDDEN];
__device__ __half g_quwh [NHEADS*HD*QC];
__device__ __half g_qrwh [NHEADS*RD*QC];
__device__ __half g_owh  [HIDDEN*NHEADS*HD];

// ======================= mma / ldmatrix helpers =============================
__device__ __forceinline__ uint32_t s2u(const void* p) {
    return (uint32_t)__cvta_generic_to_shared(p);
}
__device__ __forceinline__ void ldsm4(uint32_t* r, uint32_t addr) {
    asm volatile("ldmatrix.sync.aligned.m8n8.x4.shared.b16 {%0,%1,%2,%3}, [%4];"
                 : "=r"(r[0]), "=r"(r[1]), "=r"(r[2]), "=r"(r[3]) : "r"(addr));
}
__device__ __forceinline__ void ldsm4t(uint32_t* r, uint32_t addr) {
    asm volatile("ldmatrix.sync.aligned.m8n8.x4.trans.shared.b16 {%0,%1,%2,%3}, [%4];"
                 : "=r"(r[0]), "=r"(r[1]), "=r"(r[2]), "=r"(r[3]) : "r"(addr));
}
__device__ __forceinline__ void mmah(float* c, const uint32_t* a, const uint32_t* b) {
    asm volatile(
        "mma.sync.aligned.m16n8k16.row.col.f32.f16.f16.f32 "
        "{%0,%1,%2,%3}, {%4,%5,%6,%7}, {%8,%9}, {%0,%1,%2,%3};"
        : "+f"(c[0]), "+f"(c[1]), "+f"(c[2]), "+f"(c[3])
        : "r"(a[0]), "r"(a[1]), "r"(a[2]), "r"(a[3]), "r"(b[0]), "r"(b[1]));
}
__device__ __forceinline__ void mmahs(float* c, const uint32_t* a, uint32_t b0, uint32_t b1) {
    asm volatile(
        "mma.sync.aligned.m16n8k16.row.col.f32.f16.f16.f32 "
        "{%0,%1,%2,%3}, {%4,%5,%6,%7}, {%8,%9}, {%0,%1,%2,%3};"
        : "+f"(c[0]), "+f"(c[1]), "+f"(c[2]), "+f"(c[3])
        : "r"(a[0]), "r"(a[1]), "r"(a[2]), "r"(a[3]), "r"(b0), "r"(b1));
}
__device__ __forceinline__ void cpasync16(uint32_t dst, const void* src) {
    asm volatile("cp.async.cg.shared.global [%0], [%1], 16;"
                 :: "r"(dst), "l"(src) : "memory");
}
__device__ __forceinline__ uint32_t pack2h(float x, float y) {
    __half2 t = __floats2half2_rn(x, y);
    return *(uint32_t*)&t;
}
__device__ __forceinline__ void whi2(__half* __restrict__ H, size_t o, float a, float b) {
    *(__half2*)&H[o] = __floats2half2_rn(a, b);
}

// ======================= fp32 -> fp16 convert ===============================
__global__ void conv_half(const float* __restrict__ s, __half* __restrict__ h, int n)
{
    int i = (blockIdx.x * blockDim.x + threadIdx.x) * 4;
    if (i >= n) return;
    float4 v = *(const float4*)(s + i);
    *(__half2*)(h + i)     = __floats2half2_rn(v.x, v.y);
    *(__half2*)(h + i + 2) = __floats2half2_rn(v.z, v.w);
}

// ======= fused transpose: 4 matrices, src[K][N] fp32 -> dst [N][K] fp16 =====
struct TSpec { const float* src; __half* dst; int K; int N; int blk0; };
struct TTab  { TSpec e[4]; };

__global__ void transpose_all(TTab tab)
{
    __shared__ float t[32][33];
    int b = blockIdx.x;
    int ei = 0;
#pragma unroll
    for (int i = 1; i < 4; i++)
        if (b >= tab.e[i].blk0) ei = i;
    const TSpec sp = tab.e[ei];
    int lb = b - sp.blk0;
    int nbx = sp.N >> 5;
    int nb = (lb % nbx) * 32;
    int kb = (lb / nbx) * 32;

    int tx = threadIdx.x, ty = threadIdx.y;    // 32 x 8
#pragma unroll
    for (int i = 0; i < 32; i += 8)
        t[ty + i][tx] = sp.src[(size_t)(kb + ty + i) * sp.N + nb + tx];
    __syncthreads();
#pragma unroll
    for (int i = 0; i < 32; i += 8)
        sp.dst[(size_t)(nb + ty + i) * sp.K + kb + tx] = __float2half_rn(t[tx][ty + i]);
}

// ======================= HMMA fp16 GEMM =====================================
// C[M,N] = Ah[M,K] @ Bh[N,K]^T + bias.  CTA 128x128, 4 warps (warp tile 64x64),
// BK=32, 3-stage cp.async, 2 CTAs/SM.  Epilogue modes:
//   0 = fp32 C;  1 = fp16 [M,N];  2 = fp16 [B,H,S,192];  3 = fp16 [B,H,S,128]
#define BKP 40
#define MAT_SMEM (128*BKP*2)      // 10240
#define STG_SMEM (2*MAT_SMEM)     // 20480
#define GEMM_SMEM (3*STG_SMEM)    // 61440

__global__ void __launch_bounds__(128, 2) gemm_hmma1(
    const __half* __restrict__ Ah, const __half* __restrict__ Bh,
    const float* __restrict__ bias, float* __restrict__ C,
    __half* __restrict__ Ch,
    int M, int N, int K, int mode)
{
    extern __shared__ char dsm[];
    const uint32_t sbase = s2u(dsm);

    const int tid  = threadIdx.x;
    const int warp = tid >> 5, lane = tid & 31;
    const int wm = (warp & 1) * 64;
    const int wn = (warp >> 1) * 64;
    const int m0 = blockIdx.y * 128, n0 = blockIdx.x * 128;

    const __half* gM[2] = { Ah + (size_t)m0 * K, Bh + (size_t)n0 * K };

    const int nK = K >> 5;

    const int a_r  = lane & 15;
    const int a_c8 = (lane >> 4) << 3;
    const int b_r  = (lane & 7) + ((lane >> 4) << 3);
    const int b_c8 = (lane & 8) ? 8 : 0;

    float acc[4][8][4];
#pragma unroll
    for (int mt = 0; mt < 4; mt++)
#pragma unroll
        for (int nt = 0; nt < 8; nt++)
#pragma unroll
            for (int q = 0; q < 4; q++) acc[mt][nt][q] = 0.f;

    auto load_stage = [&](int stg, int kb) {
        uint32_t sb = sbase + stg * STG_SMEM;
#pragma unroll
        for (int mat = 0; mat < 2; mat++) {
            const __half* g = gM[mat];
#pragma unroll
            for (int j = 0; j < 4; j++) {
                int c = tid + j * 128;
                int row = c >> 2, c16 = c & 3;
                cpasync16(sb + mat * MAT_SMEM + (row * BKP + c16 * 8) * 2,
                          g + (size_t)row * K + kb + c16 * 8);
            }
        }
        asm volatile("cp.async.commit_group;" ::: "memory");
    };

    load_stage(0, 0);
    load_stage(1, 32);

    int cur = 0, nxt = 2;
    for (int i = 0; i < nK; i++) {
        if (i + 1 < nK) asm volatile("cp.async.wait_group 1;" ::: "memory");
        else            asm volatile("cp.async.wait_group 0;" ::: "memory");
        __syncthreads();
        if (i + 2 < nK) load_stage(nxt, (i + 2) * 32);

        const uint32_t sAh = sbase + cur * STG_SMEM;
        const uint32_t sBh = sAh + MAT_SMEM;

#pragma unroll
        for (int kk = 0; kk < 32; kk += 16) {
            uint32_t ah[4][4], bh[4][4];
#pragma unroll
            for (int mt = 0; mt < 4; mt++) {
                uint32_t off = ((wm + mt * 16 + a_r) * BKP + kk + a_c8) * 2;
                ldsm4(ah[mt], sAh + off);
            }
#pragma unroll
            for (int p = 0; p < 4; p++) {
                uint32_t off = ((wn + p * 16 + b_r) * BKP + kk + b_c8) * 2;
                ldsm4(bh[p], sBh + off);
            }
#pragma unroll
            for (int mt = 0; mt < 4; mt++)
#pragma unroll
                for (int nt = 0; nt < 8; nt++)
                    mmah(acc[mt][nt], ah[mt], &bh[nt >> 1][(nt & 1) * 2]);
        }
        cur = (cur == 2) ? 0 : cur + 1;
        nxt = (nxt == 2) ? 0 : nxt + 1;
    }

    // ---- epilogue ----
    const int er = lane >> 2, ec = (lane & 3) * 2;
#pragma unroll
    for (int mt = 0; mt < 4; mt++) {
#pragma unroll
        for (int nt = 0; nt < 8; nt++) {
            int col = n0 + wn + nt * 8 + ec;
            float b0 = bias[col], b1 = bias[col + 1];
            int r0 = m0 + wm + mt * 16 + er;
            int r1 = r0 + 8;
            float p0 = acc[mt][nt][0] + b0, p1 = acc[mt][nt][1] + b1;
            float p2 = acc[mt][nt][2] + b0, p3 = acc[mt][nt][3] + b1;
            if (mode == 0) {
                *(float2*)&C[(size_t)r0 * N + col] = make_float2(p0, p1);
                *(float2*)&C[(size_t)r1 * N + col] = make_float2(p2, p3);
            } else if (mode == 1) {
                whi2(Ch, (size_t)r0 * N + col, p0, p1);
                whi2(Ch, (size_t)r1 * N + col, p2, p3);
            } else {
                int hh = col >> 7, d = col & 127;
                int stride = (mode == 2) ? DQK : HD;
                size_t o0 = (((size_t)(r0 >> 11) * NHEADS + hh) * SEQ + (r0 & 2047)) * stride + d;
                size_t o1 = (((size_t)(r1 >> 11) * NHEADS + hh) * SEQ + (r1 & 2047)) * stride + d;
                whi2(Ch, o0, p0, p1);
                whi2(Ch, o1, p2, p3);
            }
        }
    }
}

// ------- RoPE into last 64 dims of K/Q --------------------------------------
__global__ void rope_pack(const float* __restrict__ kr, const float* __restrict__ qr,
                          __half* __restrict__ Kh, __half* __restrict__ Qh)
{
    int idx = blockIdx.x * blockDim.x + threadIdx.x;
    if (idx >= ROWS*NHEADS*(RD/2)) return;
    int i  = idx & 31;
    int h  = (idx >> 5) & 15;
    int bs = idx >> 9;
    int b  = bs >> 11;
    int s  = bs & 2047;
    float inv_freq = powf(10000.f, -(float)(2*i) / 64.f);
    float ang = (float)s * inv_freq;
    float sn, cs;
    sincosf(ang, &sn, &cs);
    size_t ib = (size_t)bs * (NHEADS*RD) + h*RD + 2*i;
    size_t ob = (((size_t)b*NHEADS + h)*SEQ + s)*DQK + HD + 2*i;
    float x1 = kr[ib], x2 = kr[ib+1];
    whi2(Kh, ob, x1*cs - x2*sn, x1*sn + x2*cs);
    x1 = qr[ib]; x2 = qr[ib+1];
    whi2(Qh, ob, x1*cs - x2*sn, x1*sn + x2*cs);
}

// ============== HMMA fp16 causal flash attention ============================
// CTA: 128 queries x full head. 8 warps, warp = 16 query rows.
// LPT: blockIdx.x reversed so heavy (high-q0) CTAs schedule first.
#define AQH 0
#define AKB(buf) (49152 + (buf)*24576)
#define AVB 98304
#define ATTN_SMEM 114688

__global__ void __launch_bounds__(256, 1) attn_hmma(
    const __half* __restrict__ Qhg,
    const __half* __restrict__ Khg, const __half* __restrict__ Vhg,
    __half* __restrict__ cxh)
{
    extern __shared__ char smc[];
    const uint32_t sb = s2u(smc);
    const int b = blockIdx.z, h = blockIdx.y;
    const int q0 = (gridDim.x - 1 - blockIdx.x) * 128;   // LPT: heavy first
    const int tid = threadIdx.x, w = tid >> 5, lane = tid & 31;
    const int ntiles = (q0 >> 6) + 2;

    const size_t hb = (size_t)(b*NHEADS + h) * SEQ;
    const __half* gQh = Qhg + (hb + q0) * DQK;
    const __half* gKh = Khg + hb * DQK;
    const __half* gVh = Vhg + hb * HD;

    auto ldQ = [&](uint32_t dst, const __half* g) {
        for (int i = tid; i < 128*24; i += 256) {
            int r = i / 24, c = i % 24;
            int cs = (c & ~7) | ((c ^ r) & 7);
            cpasync16(dst + (r*24 + cs)*16, g + r*192 + c*8);
        }
    };
    auto ldK = [&](uint32_t dst, const __half* g) {
        for (int i = tid; i < 64*24; i += 256) {
            int r = i / 24, c = i % 24;
            int cs = (c & ~7) | ((c ^ r) & 7);
            cpasync16(dst + (r*24 + cs)*16, g + r*192 + c*8);
        }
    };
    auto ldV = [&](uint32_t dst, const __half* g) {
        for (int i = tid; i < 64*16; i += 256) {
            int r = i / 16, c = i % 16;
            int cs = (c & ~7) | ((c ^ r) & 7);
            cpasync16(dst + (r*16 + cs)*16, g + r*128 + c*8);
        }
    };

    // prologue: group0 = {Q, K0, V0}, group1 = {K1}
    ldQ(sb + AQH, gQh);
    ldK(sb + AKB(0), gKh);
    ldV(sb + AVB,    gVh);
    asm volatile("cp.async.commit_group;" ::: "memory");
    ldK(sb + AKB(1), gKh + 64*192);
    asm volatile("cp.async.commit_group;" ::: "memory");

    float O[16][4];
#pragma unroll
    for (int t = 0; t < 16; t++)
#pragma unroll
        for (int j = 0; j < 4; j++) O[t][j] = 0.f;
    float m0r = -1e30f, m1r = -1e30f, l0 = 0.f, l1 = 0.f;

    const float scale = 0.07216878364870323f;  // 1/sqrt(192)
    const int lrow = lane & 15, lhi = lane >> 4;
    const int qr0 = q0 + w*16 + (lane >> 2);

    for (int i = 0; i < ntiles; i++) {
        const int k0 = i * 64;
        asm volatile("cp.async.wait_group 1;" ::: "memory");
        __syncthreads();

        const uint32_t kbh = sb + AKB(i & 1);

        float s[8][4];
#pragma unroll
        for (int t = 0; t < 8; t++)
#pragma unroll
            for (int j = 0; j < 4; j++) s[t][j] = 0.f;

        // ---- S = Q K^T ----
#pragma unroll
        for (int kc = 0; kc < 12; kc++) {
            uint32_t ah[4];
            {
                int r = w*16 + lrow;
                int c = kc*2 + lhi;
                int cs = (c & ~7) | ((c ^ r) & 7);
                ldsm4(ah, sb + AQH + (r*24 + cs)*16);
            }
#pragma unroll
            for (int kg = 0; kg < 4; kg++) {
                uint32_t bh[4];
                int r = kg*16 + lrow;
                int c = kc*2 + lhi;
                int cs = (c & ~7) | ((c ^ r) & 7);
                ldsm4(bh, kbh + (r*24 + cs)*16);
                mmahs(s[kg*2],   ah, bh[0], bh[2]);
                mmahs(s[kg*2+1], ah, bh[1], bh[3]);
            }
        }

        // ---- online softmax ----
        if (k0 + 63 > q0 + w*16) {
#pragma unroll
            for (int t = 0; t < 8; t++) {
                int kb = k0 + t*8 + ((lane & 3) << 1);
                s[t][0] = (kb     <= qr0    ) ? s[t][0]*scale : -1e30f;
                s[t][1] = (kb + 1 <= qr0    ) ? s[t][1]*scale : -1e30f;
                s[t][2] = (kb     <= qr0 + 8) ? s[t][2]*scale : -1e30f;
                s[t][3] = (kb + 1 <= qr0 + 8) ? s[t][3]*scale : -1e30f;
            }
        } else {
#pragma unroll
            for (int t = 0; t < 8; t++)
#pragma unroll
                for (int j = 0; j < 4; j++) s[t][j] *= scale;
        }

        float mx0 = -1e30f, mx1 = -1e30f;
#pragma unroll
        for (int t = 0; t < 8; t++) {
            mx0 = fmaxf(mx0, fmaxf(s[t][0], s[t][1]));
            mx1 = fmaxf(mx1, fmaxf(s[t][2], s[t][3]));
        }
        mx0 = fmaxf(mx0, __shfl_xor_sync(0xffffffffu, mx0, 1));
        mx0 = fmaxf(mx0, __shfl_xor_sync(0xffffffffu, mx0, 2));
        mx1 = fmaxf(mx1, __shfl_xor_sync(0xffffffffu, mx1, 1));
        mx1 = fmaxf(mx1, __shfl_xor_sync(0xffffffffu, mx1, 2));

        float mn0 = fmaxf(m0r, mx0), mn1 = fmaxf(m1r, mx1);
        float al0 = __expf(m0r - mn0), al1 = __expf(m1r - mn1);
        m0r = mn0; m1r = mn1;

        float sum0 = 0.f, sum1 = 0.f;
#pragma unroll
        for (int t = 0; t < 8; t++) {
            s[t][0] = __expf(s[t][0] - mn0); sum0 += s[t][0];
            s[t][1] = __expf(s[t][1] - mn0); sum0 += s[t][1];
            s[t][2] = __expf(s[t][2] - mn1); sum1 += s[t][2];
            s[t][3] = __expf(s[t][3] - mn1); sum1 += s[t][3];
        }
        l0 = l0*al0 + sum0;
        l1 = l1*al1 + sum1;
#pragma unroll
        for (int t = 0; t < 16; t++) {
            O[t][0] *= al0; O[t][1] *= al0;
            O[t][2] *= al1; O[t][3] *= al1;
        }

        // ---- O += P V ----
#pragma unroll
        for (int kc2 = 0; kc2 < 4; kc2++) {
            uint32_t pha[4];
            pha[0] = pack2h(s[kc2*2][0],   s[kc2*2][1]);
            pha[1] = pack2h(s[kc2*2][2],   s[kc2*2][3]);
            pha[2] = pack2h(s[kc2*2+1][0], s[kc2*2+1][1]);
            pha[3] = pack2h(s[kc2*2+1][2], s[kc2*2+1][3]);
#pragma unroll
            for (int dg = 0; dg < 8; dg++) {
                uint32_t vh[4];
                int r = kc2*16 + lrow;
                int c = dg*2 + lhi;
                int cs = (c & ~7) | ((c ^ r) & 7);
                ldsm4t(vh, sb + AVB + (r*16 + cs)*16);
                mmahs(O[dg*2],   pha, vh[0], vh[1]);
                mmahs(O[dg*2+1], pha, vh[2], vh[3]);
            }
        }
        __syncthreads();

        if (i + 1 < ntiles)
            ldV(sb + AVB, gVh + (size_t)(k0 + 64)*HD);
        asm volatile("cp.async.commit_group;" ::: "memory");
        if (i + 2 < ntiles)
            ldK(sb + AKB(i & 1), gKh + (size_t)(k0 + 128)*DQK);
        asm volatile("cp.async.commit_group;" ::: "memory");
    }

    l0 += __shfl_xor_sync(0xffffffffu, l0, 1);
    l0 += __shfl_xor_sync(0xffffffffu, l0, 2);
    l1 += __shfl_xor_sync(0xffffffffu, l1, 1);
    l1 += __shfl_xor_sync(0xffffffffu, l1, 2);
    float inv0 = 1.f / l0, inv1 = 1.f / l1;

#pragma unroll
    for (int t = 0; t < 16; t++) {
        int d = h*HD + t*8 + ((lane & 3) << 1);
        size_t ro0 = (size_t)(b*SEQ + qr0    ) * (NHEADS*HD) + d;
        size_t ro1 = (size_t)(b*SEQ + qr0 + 8) * (NHEADS*HD) + d;
        whi2(cxh, ro0, O[t][0]*inv0, O[t][1]*inv0);
        whi2(cxh, ro1, O[t][2]*inv1, O[t][3]*inv1);
    }
}

// ---------------- launch -----------------------------------------------------
static inline void gemm_s(cudaStream_t st,
                          const __half* Ah, const __half* Bh,
                          const float* bias, float* C, __half* Ch,
                          int M, int N, int K, int mode)
{
    gemm_hmma1<<<dim3(N/128, M/128), 128, GEMM_SMEM, st>>>(
        Ah, Bh, bias, C, Ch, M, N, K, mode);
}

extern "C" void kernel_launch(void* const* d_in, const int* in_sizes, int n_in,
                              void* d_out, int out_size)
{
    const float* x    = (const float*)d_in[0];
    const float* kvdw = (const float*)d_in[2];
    const float* kvdb = (const float*)d_in[3];
    const float* kuw  = (const float*)d_in[4];
    const float* kub  = (const float*)d_in[5];
    const float* vuw  = (const float*)d_in[6];
    const float* vub  = (const float*)d_in[7];
    const float* krw  = (const float*)d_in[8];
    const float* krb  = (const float*)d_in[9];
    const float* qdw  = (const float*)d_in[10];
    const float* qdb  = (const float*)d_in[11];
    const float* quw  = (const float*)d_in[12];
    const float* qub  = (const float*)d_in[13];
    const float* qrw  = (const float*)d_in[14];
    const float* qrb  = (const float*)d_in[15];
    const float* ow   = (const float*)d_in[16];
    const float* obv  = (const float*)d_in[17];
    float* out = (float*)d_out;

    float *kr, *qru;
    cudaGetSymbolAddress((void**)&kr,   g_kr);
    cudaGetSymbolAddress((void**)&qru,  g_qru);

    __half *Qh,*Kh,*Vh;
    cudaGetSymbolAddress((void**)&Qh, g_Qh);
    cudaGetSymbolAddress((void**)&Kh, g_Kh);
    cudaGetSymbolAddress((void**)&Vh, g_Vh);

    __half *xh,*kvch,*qlh,*cxh;
    __half *kvdwh,*kuwh,*vuwh,*krwh,*qdwh,*quwh,*qrwh,*owh;
    cudaGetSymbolAddress((void**)&xh, g_xh);
    cudaGetSymbolAddress((void**)&kvch, g_kvch);
    cudaGetSymbolAddress((void**)&qlh, g_qlh);
    cudaGetSymbolAddress((void**)&cxh, g_cxh);
    cudaGetSymbolAddress((void**)&kvdwh, g_kvdwh);
    cudaGetSymbolAddress((void**)&kuwh, g_kuwh);
    cudaGetSymbolAddress((void**)&vuwh, g_vuwh);
    cudaGetSymbolAddress((void**)&krwh, g_krwh);
    cudaGetSymbolAddress((void**)&qdwh, g_qdwh);
    cudaGetSymbolAddress((void**)&quwh, g_quwh);
    cudaGetSymbolAddress((void**)&qrwh, g_qrwh);
    cudaGetSymbolAddress((void**)&owh, g_owh);

    cudaFuncSetAttribute(gemm_hmma1, cudaFuncAttributeMaxDynamicSharedMemorySize, GEMM_SMEM);
    cudaFuncSetAttribute(attn_hmma, cudaFuncAttributeMaxDynamicSharedMemorySize, ATTN_SMEM);

    // fork-join: q path on side stream, kv path on main (default) stream
    cudaStream_t s2;
    cudaStreamCreateWithFlags(&s2, cudaStreamNonBlocking);
    cudaEvent_t evFork, evKV, evQ;
    cudaEventCreateWithFlags(&evFork, cudaEventDisableTiming);
    cudaEventCreateWithFlags(&evKV,   cudaEventDisableTiming);
    cudaEventCreateWithFlags(&evQ,    cudaEventDisableTiming);

    // ---- prologue on main stream: kv-side weights + x convert -------------
    {
        TTab tab;
        auto set = [&](int i, const float* s, __half* d, int K, int N, int blk0) {
            tab.e[i].src = s; tab.e[i].dst = d;
            tab.e[i].K = K; tab.e[i].N = N; tab.e[i].blk0 = blk0;
        };
        int b = 0;
        set(0, kvdw, kvdwh, HIDDEN, KVC, b);       b += (KVC/32)*(HIDDEN/32);
        set(1, kuw,  kuwh,  KVC, NHEADS*HD, b);    b += (NHEADS*HD/32)*(KVC/32);
        set(2, vuw,  vuwh,  KVC, NHEADS*HD, b);    b += (NHEADS*HD/32)*(KVC/32);
        set(3, krw,  krwh,  KVC, NHEADS*RD, b);    b += (NHEADS*RD/32)*(KVC/32);
        transpose_all<<<b, dim3(32, 8)>>>(tab);
    }
    conv_half<<<ROWS*HIDDEN/4/256, 256>>>(x, xh, ROWS*HIDDEN);

    // fork: side stream waits for xh (and runs its own weight transposes)
    cudaEventRecord(evFork, 0);
    cudaStreamWaitEvent(s2, evFork, 0);

    // ---- q-side weights on side stream ------------------------------------
    {
        TTab tab;
        auto set = [&](int i, const float* s, __half* d, int K, int N, int blk0) {
            tab.e[i].src = s; tab.e[i].dst = d;
            tab.e[i].K = K; tab.e[i].N = N; tab.e[i].blk0 = blk0;
        };
        int b = 0;
        set(0, qdw, qdwh, HIDDEN, QC, b);          b += (QC/32)*(HIDDEN/32);
        set(1, quw, quwh, QC, NHEADS*HD, b);       b += (NHEADS*HD/32)*(QC/32);
        set(2, qrw, qrwh, QC, NHEADS*RD, b);       b += (NHEADS*RD/32)*(QC/32);
        set(3, ow,  owh,  NHEADS*HD, HIDDEN, b);   b += (HIDDEN/32)*(NHEADS*HD/32);
        transpose_all<<<b, dim3(32, 8), 0, s2>>>(tab);
    }

    // ---- kv path (main stream) --------------------------------------------
    gemm_s(0, xh,   kvdwh, kvdb, nullptr, kvch, ROWS, KVC,       HIDDEN, 1);
    gemm_s(0, kvch, kuwh,  kub,  nullptr, Kh,   ROWS, NHEADS*HD, KVC,    2);
    gemm_s(0, kvch, vuwh,  vub,  nullptr, Vh,   ROWS, NHEADS*HD, KVC,    3);
    gemm_s(0, kvch, krwh,  krb,  kr, nullptr,   ROWS, NHEADS*RD, KVC,    0);

    // ---- q path (side stream) ---------------------------------------------
    gemm_s(s2, xh,  qdwh, qdb, nullptr, qlh, ROWS, QC,        HIDDEN, 1);
    gemm_s(s2, qlh, quwh, qub, nullptr, Qh,  ROWS, NHEADS*HD, QC,     2);
    gemm_s(s2, qlh, qrwh, qrb, qru, nullptr, ROWS, NHEADS*RD, QC,     0);

    // join: main waits for q path
    cudaEventRecord(evQ, s2);
    cudaStreamWaitEvent(0, evQ, 0);

    // rope into last 64 dims
    rope_pack<<<ROWS*NHEADS*(RD/2)/256, 256>>>(kr, qru, Kh, Qh);

    // attention (fp16 HMMA)
    attn_hmma<<<dim3(SEQ/128, NHEADS, BATCH), 256, ATTN_SMEM>>>(Qh, Kh, Vh, cxh);

    // output projection
    gemm_s(0, cxh, owh, obv, out, nullptr, ROWS, HIDDEN, NHEADS*HD, 0);

    // make side stream depend on completion so later harness syncs see it done
    cudaEventRecord(evKV, 0);
    cudaStreamWaitEvent(s2, evKV, 0);
}